// round 10
// baseline (speedup 1.0000x reference)
#include <cuda_runtime.h>
#include <math.h>

#define Bsz   256
#define Tlen  1024
#define Hdim  128
#define NBLK  128      // 8 batch-tiles x 16 unit-tiles
#define NTHR  256
#define MT    32       // batches per CTA
#define UT    8        // hidden units per CTA (x4 gates = 32 rows)

// k2 (k-pair) bounds; slot map: 0=x, 1=zero, 2..129=h1, 130..257=h2, 258..385=h3
#define K2_1  65       // x+h1 part: k2 [0,65)
#define K2_2  129      // + h2 part: k2 [65,129)
#define K2_3  193      // + h3 part: k2 [129,193)

// ---- shared memory layout (float offsets) ----
#define OFF_W1 0
#define OFF_W2 (OFF_W1 + K2_1*64)       // 4160
#define OFF_W3 (OFF_W2 + K2_2*64)       // 12416
#define OFF_A  (OFF_W3 + K2_3*64)       // 24768  activations: float2 a2[k2][32] -> floats [k2*64 + m*2 + j]
#define OFF_G  (OFF_A  + K2_3*64)       // 37120  gate partials: 4 x [32 rows][32 m]
#define OFF_C  (OFF_G  + 4096)          // 41216  c state [3][8][32]
#define OFF_BS (OFF_C  + 768)           // 41984  combined biases [3][32]
#define OFF_WL (OFF_BS + 96)            // 42080  W_lin in slot space [388] (== float2[194])
#define OFF_OP (OFF_WL + 388)           // 42468  o partials [8][32]
#define OFF_BL (OFF_OP + 256)           // 42724  b_lin
#define SMEM_FLOATS (OFF_BL + 4)        // 42728
#define SMEM_BYTES  (SMEM_FLOATS*4)     // 170912 bytes -> 1 CTA/SM

// ---- global scratch ----
__device__ __align__(256) float g_h[3][Hdim][Bsz];   // [layer][unit][batch]
__device__ unsigned g_flag[8][3][16][32];            // one 128B line per flag

__device__ __forceinline__ unsigned ld_acq(const unsigned* p) {
    unsigned v;
    asm volatile("ld.acquire.gpu.u32 %0, [%1];" : "=r"(v) : "l"(p) : "memory");
    return v;
}
__device__ __forceinline__ void st_rel(unsigned* p, unsigned v) {
    asm volatile("st.release.gpu.u32 [%0], %1;" :: "l"(p), "r"(v) : "memory");
}

// 16-row x 32-batch GEMM over k2 in [lo,hi).
// Lane (rg=lane>>3, bg=lane&7) owns rows [16rg2+4rg .. +3] x batches [4bg .. +3].
// acc[q*4+i] is f32x2 (even-k, odd-k partial) for (row q, batch i).
__device__ __forceinline__ void gemm16(const float* __restrict__ wb,
                                       const float* __restrict__ a2f,
                                       int woff, int aoff, int lo, int hi,
                                       unsigned long long* __restrict__ acc)
{
    const char* wp = (const char*)wb  + (size_t)woff*4;
    const char* ap = (const char*)a2f + (size_t)aoff*4;
#pragma unroll 2
    for (int k2 = lo; k2 < hi; k2++) {
        ulonglong2 w01 = *(const ulonglong2*)(wp + (size_t)k2*256);        // rows q0,q1
        ulonglong2 w23 = *(const ulonglong2*)(wp + (size_t)k2*256 + 16);   // rows q2,q3
        ulonglong2 a01 = *(const ulonglong2*)(ap + (size_t)k2*256);        // batches i0,i1
        ulonglong2 a23 = *(const ulonglong2*)(ap + (size_t)k2*256 + 16);   // batches i2,i3
        asm("fma.rn.f32x2 %0, %1, %2, %0;" : "+l"(acc[ 0]) : "l"(a01.x), "l"(w01.x));
        asm("fma.rn.f32x2 %0, %1, %2, %0;" : "+l"(acc[ 1]) : "l"(a01.y), "l"(w01.x));
        asm("fma.rn.f32x2 %0, %1, %2, %0;" : "+l"(acc[ 2]) : "l"(a23.x), "l"(w01.x));
        asm("fma.rn.f32x2 %0, %1, %2, %0;" : "+l"(acc[ 3]) : "l"(a23.y), "l"(w01.x));
        asm("fma.rn.f32x2 %0, %1, %2, %0;" : "+l"(acc[ 4]) : "l"(a01.x), "l"(w01.y));
        asm("fma.rn.f32x2 %0, %1, %2, %0;" : "+l"(acc[ 5]) : "l"(a01.y), "l"(w01.y));
        asm("fma.rn.f32x2 %0, %1, %2, %0;" : "+l"(acc[ 6]) : "l"(a23.x), "l"(w01.y));
        asm("fma.rn.f32x2 %0, %1, %2, %0;" : "+l"(acc[ 7]) : "l"(a23.y), "l"(w01.y));
        asm("fma.rn.f32x2 %0, %1, %2, %0;" : "+l"(acc[ 8]) : "l"(a01.x), "l"(w23.x));
        asm("fma.rn.f32x2 %0, %1, %2, %0;" : "+l"(acc[ 9]) : "l"(a01.y), "l"(w23.x));
        asm("fma.rn.f32x2 %0, %1, %2, %0;" : "+l"(acc[10]) : "l"(a23.x), "l"(w23.x));
        asm("fma.rn.f32x2 %0, %1, %2, %0;" : "+l"(acc[11]) : "l"(a23.y), "l"(w23.x));
        asm("fma.rn.f32x2 %0, %1, %2, %0;" : "+l"(acc[12]) : "l"(a01.x), "l"(w23.y));
        asm("fma.rn.f32x2 %0, %1, %2, %0;" : "+l"(acc[13]) : "l"(a01.y), "l"(w23.y));
        asm("fma.rn.f32x2 %0, %1, %2, %0;" : "+l"(acc[14]) : "l"(a23.x), "l"(w23.y));
        asm("fma.rn.f32x2 %0, %1, %2, %0;" : "+l"(acc[15]) : "l"(a23.y), "l"(w23.y));
    }
}

// gates: STS.128 per row (4 consecutive m), structural-min wavefronts
__device__ __forceinline__ void store_gates16(float* __restrict__ gsh, int kq,
                                              int rg2, int rg, int bg,
                                              const unsigned long long* __restrict__ acc)
{
    float* gp = gsh + kq*1024 + (16*rg2 + 4*rg)*32 + 4*bg;
#pragma unroll
    for (int q = 0; q < 4; q++) {
        float4 v;
        float lo, hi;
        asm("mov.b64 {%0, %1}, %2;" : "=f"(lo), "=f"(hi) : "l"(acc[q*4+0])); v.x = lo + hi;
        asm("mov.b64 {%0, %1}, %2;" : "=f"(lo), "=f"(hi) : "l"(acc[q*4+1])); v.y = lo + hi;
        asm("mov.b64 {%0, %1}, %2;" : "=f"(lo), "=f"(hi) : "l"(acc[q*4+2])); v.z = lo + hi;
        asm("mov.b64 {%0, %1}, %2;" : "=f"(lo), "=f"(hi) : "l"(acc[q*4+3])); v.w = lo + hi;
        *(float4*)(gp + q*32) = v;
    }
}

__device__ __forceinline__ float sigm(float v) {
    return __fdividef(1.f, 1.f + __expf(-v));
}
__device__ __forceinline__ float tanh_fast(float v) {
    return 1.f - __fdividef(2.f, __expf(2.f*v) + 1.f);
}

// combine 4 split-k partials + bias, update c (SMEM), write h to global L2
__device__ __forceinline__ void cell_update(int layer, int u, int m, int nt, int m0,
                                            const float* __restrict__ gsh,
                                            const float* __restrict__ bs,
                                            float* __restrict__ csh,
                                            float* __restrict__ hglob)
{
#define GSUM(r) (gsh[(r)*32+m] + gsh[1024+(r)*32+m] + gsh[2048+(r)*32+m] + gsh[3072+(r)*32+m])
    float xi = GSUM( 0 + u) + bs[ 0 + u];
    float xf = GSUM( 8 + u) + bs[ 8 + u];
    float xg = GSUM(16 + u) + bs[16 + u];
    float xo = GSUM(24 + u) + bs[24 + u];
#undef GSUM
    float ii = sigm(xi);
    float ff = sigm(xf);
    float gg = tanh_fast(xg);
    float oo = sigm(xo);
    float* cp = csh + layer*(UT*32) + u*32 + m;
    float c = ff * cp[0] + ii * gg;
    cp[0] = c;
    hglob[(nt*UT + u)*Bsz + m0 + m] = oo * tanh_fast(c);
}

// fused spin + refresh: warp wi waits for producers {2wi, 2wi+1}, pulls their
// 8x32 h slices into a2 as packed float2 (units 2u, 2u+1 -> one slot pair).
// STS.64 with m=lane: conflict-free (structural 2-wf).
__device__ __forceinline__ void wait_refresh(int mt, int ph, unsigned tok, int wi, int lane,
                                             const float* __restrict__ hg,
                                             float* __restrict__ a2f, int sbase, int m0)
{
#pragma unroll
    for (int j = 0; j < 2; j++) {
        int p = 2*wi + j;
        const unsigned* fp = &g_flag[mt][ph][p][0];
        unsigned v;
        do { v = ld_acq(fp); } while ((int)(v - tok) < 0);
        const float* hp = hg + (p*8)*Bsz + m0 + lane;
#pragma unroll
        for (int up = 0; up < 4; up++) {
            float v0 = __ldcg(hp + (2*up    )*Bsz);
            float v1 = __ldcg(hp + (2*up + 1)*Bsz);
            int s = sbase + p*8 + 2*up;               // even slot
            float2* dst = (float2*)(a2f + (s >> 1)*64) + lane;
            *dst = make_float2(v0, v1);
        }
    }
}

__global__ void __launch_bounds__(NTHR, 1)
lstm_forecast_kernel(const float* __restrict__ x,
                     const float* __restrict__ Wih1, const float* __restrict__ Whh1,
                     const float* __restrict__ bih1, const float* __restrict__ bhh1,
                     const float* __restrict__ Wih2, const float* __restrict__ Whh2,
                     const float* __restrict__ bih2, const float* __restrict__ bhh2,
                     const float* __restrict__ Wih3, const float* __restrict__ Whh3,
                     const float* __restrict__ bih3, const float* __restrict__ bhh3,
                     const float* __restrict__ Wlin, const float* __restrict__ blin,
                     float* __restrict__ out, int fut)
{
    extern __shared__ float sm[];
    const int tid  = threadIdx.x;
    const int lane = tid & 31;
    const int wi   = tid >> 5;
    const int rg2  = wi & 1;            // row group: rows 16*rg2 .. +15
    const int kq   = wi >> 1;           // k-quarter 0..3
    const int rg   = lane >> 3;         // rows 4rg..4rg+3 within group
    const int bg   = lane & 7;          // batches 4bg..4bg+3
    const int mt   = blockIdx.x >> 4;   // batch tile 0..7
    const int nt   = blockIdx.x & 15;   // unit tile 0..15
    const int m0   = mt * MT;

    float* w1  = sm + OFF_W1;
    float* w2p = sm + OFF_W2;
    float* w3p = sm + OFF_W3;
    float* a2f = sm + OFF_A;
    float* gsh = sm + OFF_G;
    float* csh = sm + OFF_C;
    float* bsh = sm + OFF_BS;
    float* wls = sm + OFF_WL;
    float* ops = sm + OFF_OP;

    // ---------------- prologue: pack weight slices [k2][r2*2+j] ----------------
    for (int idx = tid; idx < K2_1*64; idx += NTHR) {
        int k2 = idx >> 6, rj = idx & 63, r = rj >> 1, j = rj & 1, s = 2*k2 + j;
        int rg_ = ((r >> 3) << 7) + nt*UT + (r & 7);
        w1[idx] = (s == 1) ? 0.f : ((s == 0) ? Wih1[rg_] : Whh1[rg_*Hdim + (s - 2)]);
    }
    for (int idx = tid; idx < K2_2*64; idx += NTHR) {
        int k2 = idx >> 6, rj = idx & 63, r = rj >> 1, j = rj & 1, s = 2*k2 + j;
        int rg_ = ((r >> 3) << 7) + nt*UT + (r & 7);
        float v;
        if (s == 1)        v = 0.f;
        else if (s == 0)   v = Wih2[rg_*129];
        else if (s < 130)  v = Wih2[rg_*129 + (s - 1)];
        else               v = Whh2[rg_*Hdim + (s - 130)];
        w2p[idx] = v;
    }
    for (int idx = tid; idx < K2_3*64; idx += NTHR) {
        int k2 = idx >> 6, rj = idx & 63, r = rj >> 1, j = rj & 1, s = 2*k2 + j;
        int rg_ = ((r >> 3) << 7) + nt*UT + (r & 7);
        float v;
        if (s == 1)        v = 0.f;
        else if (s == 0)   v = Wih3[rg_*257];
        else if (s < 258)  v = Wih3[rg_*257 + (s - 1)];
        else               v = Whh3[rg_*Hdim + (s - 258)];
        w3p[idx] = v;
    }
    if (tid < 32) {
        int r = tid;
        int rg_ = ((r >> 3) << 7) + nt*UT + (r & 7);
        bsh[0*32 + r] = bih1[rg_] + bhh1[rg_];
        bsh[1*32 + r] = bih2[rg_] + bhh2[rg_];
        bsh[2*32 + r] = bih3[rg_] + bhh3[rg_];
    }
    for (int s = tid; s < 388; s += NTHR)   // slot-order == float2[k2][j] order
        wls[s] = (s >= 386 || s == 1) ? 0.f : ((s == 0) ? Wlin[0] : Wlin[s - 1]);
    if (tid == 0) sm[OFF_BL] = blin[0];
    for (int idx = tid; idx < K2_3*64; idx += NTHR) a2f[idx] = 0.f;   // h(-1)=0, pad=0
    for (int idx = tid; idx < 3*UT*32; idx += NTHR) csh[idx] = 0.f;

    // replay-safe token base (all flags equal at launch entry; only we write ours)
    const unsigned base = ld_acq(&g_flag[mt][0][nt][0]);
    __syncthreads();

    const int Ttot = Tlen + fut;
    const int u = wi;        // cell-update mapping (unit = warp, batch = lane)
    const int m = lane;
    const float blv = sm[OFF_BL];
    const int woff = 32*rg2 + 8*rg;     // warp/lane weight float offset
    const int aoff = 8*bg;              // lane activation float offset

    // per-warp k2 quarter bounds
    const int xlo = (K2_1*kq) >> 2, xhi = (K2_1*(kq+1)) >> 2;   // x+h1 [0,65)
    const int r2lo = K2_1 + 16*kq, r2hi = r2lo + 16;            // h2   [65,129)
    const int r3lo = K2_2 + 16*kq, r3hi = r3lo + 16;            // h3   [129,193)

    const ulonglong1* wl2 = (const ulonglong1*)wls;             // f32x2 view of W_lin

    float xv = 0.f;
    if (tid < 32) xv = x[(m0 + tid)*Tlen + 0];

    for (int t = 0; t < Ttot; t++) {
        const unsigned tok0 = base + 3u*(unsigned)t + 1u;
        const unsigned tok1 = tok0 + 1u;
        const unsigned tok2 = tok0 + 2u;

        if (t < Tlen && tid < 32) a2f[tid*2] = xv;               // slot 0 (x), slot 1 stays 0
        if (tid < 32 && t + 1 < Tlen) xv = x[(m0 + tid)*Tlen + (t + 1)];
        __syncthreads();

        // ---------- layer 1 (x + h1(t-1): local) ----------
        {
            unsigned long long acc[16] = {0,0,0,0,0,0,0,0,0,0,0,0,0,0,0,0};
            gemm16(w1, a2f, woff, aoff, xlo, xhi, acc);
            store_gates16(gsh, kq, rg2, rg, bg, acc);
        }
        __syncthreads();
        cell_update(0, u, m, nt, m0, gsh, bsh + 0, csh, &g_h[0][0][0]);
        __syncthreads();
        if (tid == 0) st_rel(&g_flag[mt][0][nt][0], tok0);

        // overlap barrier0: recurrent partials on stale h2(t-1), h3(t-1)
        unsigned long long acc2[16] = {0,0,0,0,0,0,0,0,0,0,0,0,0,0,0,0};
        unsigned long long acc3[16] = {0,0,0,0,0,0,0,0,0,0,0,0,0,0,0,0};
        gemm16(w2p, a2f, woff, aoff, r2lo, r2hi, acc2);   // W_hh2 . h2(t-1)
        gemm16(w3p, a2f, woff, aoff, r3lo, r3hi, acc3);   // W_hh3 . h3(t-1)

        wait_refresh(mt, 0, tok0, wi, lane, &g_h[0][0][0], a2f, 2, m0);    // h1(t) -> slots 2..129
        __syncthreads();

        // ---------- layer 2 finish (x + fresh h1) ----------
        gemm16(w2p, a2f, woff, aoff, xlo, xhi, acc2);
        store_gates16(gsh, kq, rg2, rg, bg, acc2);
        __syncthreads();
        cell_update(1, u, m, nt, m0, gsh, bsh + 32, csh, &g_h[1][0][0]);
        __syncthreads();
        if (tid == 0) st_rel(&g_flag[mt][1][nt][0], tok1);

        // overlap barrier1: layer3's x+h1 part
        gemm16(w3p, a2f, woff, aoff, xlo, xhi, acc3);

        wait_refresh(mt, 1, tok1, wi, lane, &g_h[1][0][0], a2f, 130, m0);  // h2(t) -> slots 130..257
        __syncthreads();

        // ---------- layer 3 finish (fresh h2) ----------
        gemm16(w3p, a2f, woff, aoff, r2lo, r2hi, acc3);
        store_gates16(gsh, kq, rg2, rg, bg, acc3);
        __syncthreads();
        cell_update(2, u, m, nt, m0, gsh, bsh + 64, csh, &g_h[2][0][0]);
        __syncthreads();
        if (tid == 0) st_rel(&g_flag[mt][2][nt][0], tok2);

        // ---------- linear head (f32x2 over k2) ----------
        const bool doo = (nt == 0) || (t >= Tlen - 1);
        unsigned long long pacc = 0;
        if (doo) {   // k2 [0,128) = x,h1,h2 all fresh — overlaps barrier2
            for (int k2 = wi; k2 < 128; k2 += 8) {
                unsigned long long av = *(const unsigned long long*)(a2f + k2*64 + lane*2);
                asm("fma.rn.f32x2 %0, %1, %2, %0;" : "+l"(pacc) : "l"(av), "l"(wl2[k2].x));
            }
        }

        wait_refresh(mt, 2, tok2, wi, lane, &g_h[2][0][0], a2f, 258, m0);  // h3(t) -> slots 258..385
        __syncthreads();

        if (doo) {
            for (int k2 = 128 + wi; k2 < 193; k2 += 8) {
                unsigned long long av = *(const unsigned long long*)(a2f + k2*64 + lane*2);
                asm("fma.rn.f32x2 %0, %1, %2, %0;" : "+l"(pacc) : "l"(av), "l"(wl2[k2].x));
            }
            float plo, phi;
            asm("mov.b64 {%0, %1}, %2;" : "=f"(plo), "=f"(phi) : "l"(pacc));
            ops[wi*32 + lane] = plo + phi;
            __syncthreads();
            if (wi == 0) {
                float o = blv;
#pragma unroll
                for (int j = 0; j < 8; j++) o += ops[j*32 + lane];
                if (nt == 0) out[(m0 + lane)*Ttot + t] = o;
                if (t >= Tlen - 1) a2f[lane*2] = o;   // feed back as next x (slot 0)
            }
        }
        // loop-top __syncthreads orders feedback write before next step's GEMM
    }
}

extern "C" void kernel_launch(void* const* d_in, const int* in_sizes, int n_in,
                              void* d_out, int out_size)
{
    const float* x    = (const float*)d_in[0];
    const float* Wih1 = (const float*)d_in[1];
    const float* Whh1 = (const float*)d_in[2];
    const float* bih1 = (const float*)d_in[3];
    const float* bhh1 = (const float*)d_in[4];
    const float* Wih2 = (const float*)d_in[5];
    const float* Whh2 = (const float*)d_in[6];
    const float* bih2 = (const float*)d_in[7];
    const float* bhh2 = (const float*)d_in[8];
    const float* Wih3 = (const float*)d_in[9];
    const float* Whh3 = (const float*)d_in[10];
    const float* bih3 = (const float*)d_in[11];
    const float* bhh3 = (const float*)d_in[12];
    const float* Wlin = (const float*)d_in[13];
    const float* blin = (const float*)d_in[14];
    (void)in_sizes; (void)n_in;

    int fut = out_size / Bsz - Tlen;

    cudaFuncSetAttribute((const void*)lstm_forecast_kernel,
                         cudaFuncAttributeMaxDynamicSharedMemorySize, SMEM_BYTES);

    lstm_forecast_kernel<<<NBLK, NTHR, SMEM_BYTES>>>(
        x, Wih1, Whh1, bih1, bhh1, Wih2, Whh2, bih2, bhh2,
        Wih3, Whh3, bih3, bhh3, Wlin, blin, (float*)d_out, fut);
}